// round 7
// baseline (speedup 1.0000x reference)
#include <cuda_runtime.h>
#include <cuda_bf16.h>

#define N_NODES 100000
#define N_EDGES 1600000
#define C       128
#define NCLS    16
#define DCAT    512   // 128 + 3*128
#define SB      1024
#define NB      ((N_NODES + SB - 1) / SB)   // 98 scan blocks

// ---- scratch (device globals: no allocation allowed) ----
__device__ float g_tmp[(size_t)N_NODES * C];   // x_prev @ W  (51.2 MB)
__device__ float g_dis[N_NODES];               // rsqrt(degree)
__device__ int   g_cnt[N_NODES];               // in-degree counts
__device__ int   g_rowstart[N_NODES + 1];      // CSR row offsets
__device__ int   g_cursor[N_NODES];            // fill cursors
__device__ int   g_bsum[NB];                   // scan block sums
__device__ int   g_boff[NB];                   // scan block offsets
__device__ int2  g_csr[N_EDGES];               // CSR: {src, dis[src] bits}
__device__ __nv_bfloat16 g_Wt_hi[3][C * C];    // W^T [n][k] hi, per layer
__device__ __nv_bfloat16 g_Wt_lo[3][C * C];    // W^T [n][k] lo, per layer

// ---------------------------------------------------------------------------
// K0: copy x into h[:,0:128] (stride 512); zero degree counters.
// ---------------------------------------------------------------------------
__global__ void k_init(const float* __restrict__ x, float* __restrict__ h) {
    int t = blockIdx.x * blockDim.x + threadIdx.x;
    if (t >= N_NODES * 32) return;
    int node = t >> 5;
    int lane = t & 31;
    float4 v = ((const float4*)(x + (size_t)node * C))[lane];
    ((float4*)(h + (size_t)node * DCAT))[lane] = v;
    if (lane == 0) g_cnt[node] = 0;
}

// K1: convert all three W[k][n] fp32 -> transposed [n][k] bf16 hi/lo
__global__ void k_wconv(const float* __restrict__ W0,
                        const float* __restrict__ W1,
                        const float* __restrict__ W2) {
    int idx = blockIdx.x * blockDim.x + threadIdx.x;
    if (idx >= 3 * C * C) return;
    int l = idx / (C * C);
    int r = idx - l * (C * C);
    const float* W = (l == 0) ? W0 : (l == 1) ? W1 : W2;
    int k = r >> 7;
    int n = r & 127;
    float v = W[r];
    __nv_bfloat16 hi = __float2bfloat16_rn(v);
    float lo = v - __bfloat162float(hi);
    g_Wt_hi[l][n * C + k] = hi;
    g_Wt_lo[l][n * C + k] = __float2bfloat16_rn(lo);
}

// K2: in-degree count. edge_index is int32: row0 = src, row1 = dst.
__global__ void k_deg(const int* __restrict__ ei) {
    int e = blockIdx.x * blockDim.x + threadIdx.x;
    if (e >= N_EDGES) return;
    atomicAdd(&g_cnt[ei[N_EDGES + e]], 1);
}

// ---------------------------------------------------------------------------
// Multi-block scan
// ---------------------------------------------------------------------------
__global__ void k_scanA() {
    int i = blockIdx.x * SB + threadIdx.x;
    int lane = threadIdx.x & 31, wid = threadIdx.x >> 5;
    int v = (i < N_NODES) ? g_cnt[i] : 0;
    int s = v;
#pragma unroll
    for (int o = 1; o < 32; o <<= 1) {
        int t = __shfl_up_sync(0xffffffffu, s, o);
        if (lane >= o) s += t;
    }
    __shared__ int wsum[32];
    if (lane == 31) wsum[wid] = s;
    __syncthreads();
    if (wid == 0) {
        int t = wsum[lane];
#pragma unroll
        for (int o = 1; o < 32; o <<= 1) {
            int u = __shfl_up_sync(0xffffffffu, t, o);
            if (lane >= o) t += u;
        }
        wsum[lane] = t;
    }
    __syncthreads();
    int incl = s + (wid > 0 ? wsum[wid - 1] : 0);
    if (i < N_NODES) g_rowstart[i] = incl - v;
    if (threadIdx.x == SB - 1) g_bsum[blockIdx.x] = incl;
}

__global__ void k_scanB() {       // one block, 128 threads (NB <= 128)
    int tid = threadIdx.x;
    int lane = tid & 31, wid = tid >> 5;
    int v = (tid < NB) ? g_bsum[tid] : 0;
    int s = v;
#pragma unroll
    for (int o = 1; o < 32; o <<= 1) {
        int t = __shfl_up_sync(0xffffffffu, s, o);
        if (lane >= o) s += t;
    }
    __shared__ int wsum[4];
    if (lane == 31) wsum[wid] = s;
    __syncthreads();
    int woff = 0;
    for (int w = 0; w < wid; ++w) woff += wsum[w];
    int incl = s + woff;
    if (tid < NB) g_boff[tid] = incl - v;
    if (tid == NB - 1) g_rowstart[N_NODES] = incl;
}

__global__ void k_scanC() {
    int i = blockIdx.x * blockDim.x + threadIdx.x;
    if (i >= N_NODES) return;
    int e = g_rowstart[i] + g_boff[i >> 10];
    g_rowstart[i] = e;
    g_cursor[i]   = e;
    g_dis[i]      = rsqrtf((float)(g_cnt[i] + 1));
}

// K: bucket-fill CSR (packed int2: src + dis[src] bits)
__global__ void k_fill(const int* __restrict__ ei) {
    int e = blockIdx.x * blockDim.x + threadIdx.x;
    if (e >= N_EDGES) return;
    int s = ei[e];
    int d = ei[N_EDGES + e];
    int pos = atomicAdd(&g_cursor[d], 1);
    g_csr[pos] = make_int2(s, __float_as_int(g_dis[s]));
}

// ---------------------------------------------------------------------------
// GEMM (tensor-core, bf16 split): g_tmp = in @ W
// ---------------------------------------------------------------------------
#define APAD 40
__device__ __forceinline__ void mma_bf16(float c[4], const unsigned a[4],
                                         const unsigned b[2]) {
    asm volatile(
        "mma.sync.aligned.m16n8k16.row.col.f32.bf16.bf16.f32 "
        "{%0,%1,%2,%3}, {%4,%5,%6,%7}, {%8,%9}, {%0,%1,%2,%3};\n"
        : "+f"(c[0]), "+f"(c[1]), "+f"(c[2]), "+f"(c[3])
        : "r"(a[0]), "r"(a[1]), "r"(a[2]), "r"(a[3]), "r"(b[0]), "r"(b[1]));
}

__global__ void __launch_bounds__(256)
k_gemm_tc(const float* __restrict__ in, int layer) {
    __shared__ __nv_bfloat16 a_hi[128][APAD];
    __shared__ __nv_bfloat16 a_lo[128][APAD];
    __shared__ __nv_bfloat16 b_hi[128][APAD];
    __shared__ __nv_bfloat16 b_lo[128][APAD];

    const __nv_bfloat16* Whi = g_Wt_hi[layer];
    const __nv_bfloat16* Wlo = g_Wt_lo[layer];

    int tid  = threadIdx.x;
    int lane = tid & 31;
    int wid  = tid >> 5;
    int wm   = wid & 1;
    int wn   = wid >> 1;
    int row0 = blockIdx.x * 128;

    int arow = tid >> 1;
    int akb  = (tid & 1) * 16;
    int grow = row0 + arow;
    if (grow >= N_NODES) grow = N_NODES - 1;
    const float* aptr = in + (size_t)grow * DCAT;

    int bcol = tid >> 1;
    int bkb  = (tid & 1) * 16;

    float acc[4][4][4];
#pragma unroll
    for (int i = 0; i < 4; ++i)
#pragma unroll
        for (int j = 0; j < 4; ++j)
#pragma unroll
            for (int q = 0; q < 4; ++q) acc[i][j][q] = 0.0f;

    for (int k0 = 0; k0 < C; k0 += 32) {
        float av[16];
#pragma unroll
        for (int j = 0; j < 4; ++j) {
            float4 v = *(const float4*)(aptr + k0 + akb + j * 4);
            av[j * 4 + 0] = v.x; av[j * 4 + 1] = v.y;
            av[j * 4 + 2] = v.z; av[j * 4 + 3] = v.w;
        }
        uint4 wv_hi0 = *(const uint4*)(&Whi[bcol * C + k0 + bkb]);
        uint4 wv_hi1 = *(const uint4*)(&Whi[bcol * C + k0 + bkb + 8]);
        uint4 wv_lo0 = *(const uint4*)(&Wlo[bcol * C + k0 + bkb]);
        uint4 wv_lo1 = *(const uint4*)(&Wlo[bcol * C + k0 + bkb + 8]);

        unsigned ah[8], al[8];
#pragma unroll
        for (int j = 0; j < 8; ++j) {
            float v0 = av[2 * j], v1 = av[2 * j + 1];
            __nv_bfloat16 h0 = __float2bfloat16_rn(v0);
            __nv_bfloat16 h1 = __float2bfloat16_rn(v1);
            float l0 = v0 - __bfloat162float(h0);
            float l1 = v1 - __bfloat162float(h1);
            __nv_bfloat162 hp = __halves2bfloat162(h0, h1);
            __nv_bfloat162 lp = __halves2bfloat162(__float2bfloat16_rn(l0),
                                                   __float2bfloat16_rn(l1));
            ah[j] = *(unsigned*)&hp;
            al[j] = *(unsigned*)&lp;
        }

        __syncthreads();
        *(uint4*)&a_hi[arow][akb]     = make_uint4(ah[0], ah[1], ah[2], ah[3]);
        *(uint4*)&a_hi[arow][akb + 8] = make_uint4(ah[4], ah[5], ah[6], ah[7]);
        *(uint4*)&a_lo[arow][akb]     = make_uint4(al[0], al[1], al[2], al[3]);
        *(uint4*)&a_lo[arow][akb + 8] = make_uint4(al[4], al[5], al[6], al[7]);
        *(uint4*)&b_hi[bcol][bkb]     = wv_hi0;
        *(uint4*)&b_hi[bcol][bkb + 8] = wv_hi1;
        *(uint4*)&b_lo[bcol][bkb]     = wv_lo0;
        *(uint4*)&b_lo[bcol][bkb + 8] = wv_lo1;
        __syncthreads();

#pragma unroll
        for (int ks = 0; ks < 2; ++ks) {
            int kb = ks * 16 + (lane & 3) * 2;
            unsigned bh[4][2], bl[4][2];
#pragma unroll
            for (int ni = 0; ni < 4; ++ni) {
                int col = wn * 32 + ni * 8 + (lane >> 2);
                bh[ni][0] = *(unsigned*)&b_hi[col][kb];
                bh[ni][1] = *(unsigned*)&b_hi[col][kb + 8];
                bl[ni][0] = *(unsigned*)&b_lo[col][kb];
                bl[ni][1] = *(unsigned*)&b_lo[col][kb + 8];
            }
#pragma unroll
            for (int mi = 0; mi < 4; ++mi) {
                int r = wm * 64 + mi * 16 + (lane >> 2);
                unsigned AH[4], AL[4];
                AH[0] = *(unsigned*)&a_hi[r][kb];
                AH[1] = *(unsigned*)&a_hi[r + 8][kb];
                AH[2] = *(unsigned*)&a_hi[r][kb + 8];
                AH[3] = *(unsigned*)&a_hi[r + 8][kb + 8];
                AL[0] = *(unsigned*)&a_lo[r][kb];
                AL[1] = *(unsigned*)&a_lo[r + 8][kb];
                AL[2] = *(unsigned*)&a_lo[r][kb + 8];
                AL[3] = *(unsigned*)&a_lo[r + 8][kb + 8];
#pragma unroll
                for (int ni = 0; ni < 4; ++ni) {
                    mma_bf16(acc[mi][ni], AH, bh[ni]);
                    mma_bf16(acc[mi][ni], AL, bh[ni]);
                    mma_bf16(acc[mi][ni], AH, bl[ni]);
                }
            }
        }
    }

#pragma unroll
    for (int mi = 0; mi < 4; ++mi) {
        int r = row0 + wm * 64 + mi * 16 + (lane >> 2);
#pragma unroll
        for (int ni = 0; ni < 4; ++ni) {
            int col = wn * 32 + ni * 8 + (lane & 3) * 2;
            if (r < N_NODES) {
                *(float2*)(g_tmp + (size_t)r * C + col) =
                    make_float2(acc[mi][ni][0], acc[mi][ni][1]);
            }
            if (r + 8 < N_NODES) {
                *(float2*)(g_tmp + (size_t)(r + 8) * C + col) =
                    make_float2(acc[mi][ni][2], acc[mi][ni][3]);
            }
        }
    }
}

// ---------------------------------------------------------------------------
// Aggregation: TWO warps per node (64 channels each, float2 per lane).
// Doubles warp-level memory parallelism vs one-warp-per-node.
// ---------------------------------------------------------------------------
__global__ void k_aggr(const float* __restrict__ b, float* __restrict__ out) {
    int gw   = (blockIdx.x * blockDim.x + threadIdx.x) >> 5;
    int node = gw >> 1;
    int half = gw & 1;
    int lane = threadIdx.x & 31;
    if (node >= N_NODES) return;

    int rs = g_rowstart[node];
    int re = g_rowstart[node + 1];
    int off = half * 64 + lane * 2;        // channel offset

    float2 acc = make_float2(0.f, 0.f);
#pragma unroll 4
    for (int e = rs; e < re; ++e) {
        int2  p = g_csr[e];                // single 8B load: {src, w bits}
        float w = __int_as_float(p.y);
        float2 v = *(const float2*)(g_tmp + (size_t)p.x * C + off);
        acc.x = fmaf(v.x, w, acc.x);
        acc.y = fmaf(v.y, w, acc.y);
    }

    float di = g_dis[node];
    float d2 = di * di;
    float2 sv = *(const float2*)(g_tmp + (size_t)node * C + off);
    float2 bb = *(const float2*)(b + off);
    float2 o;
    o.x = fmaf(acc.x, di, fmaf(sv.x, d2, bb.x));
    o.y = fmaf(acc.y, di, fmaf(sv.y, d2, bb.y));
    *(float2*)(out + (size_t)node * DCAT + off) = o;
}

// ---------------------------------------------------------------------------
// Final linear: labels[N,16] = h[N,512] @ W_lin[512,16] + b_lin
// ---------------------------------------------------------------------------
__global__ void k_lin(const float* __restrict__ h, const float* __restrict__ Wl,
                      const float* __restrict__ bl, float* __restrict__ out) {
    __shared__ float ws[DCAT * 17];
    __shared__ float bs[NCLS];
    for (int idx = threadIdx.x; idx < DCAT * NCLS; idx += blockDim.x) {
        int c = idx >> 4;
        int k = idx & 15;
        ws[c * 17 + k] = Wl[idx];
    }
    if (threadIdx.x < NCLS) bs[threadIdx.x] = bl[threadIdx.x];
    __syncthreads();

    int warp = threadIdx.x >> 5;
    int lane = threadIdx.x & 31;
    int warpsPerGrid = (blockDim.x >> 5) * gridDim.x;
    for (int node = blockIdx.x * (blockDim.x >> 5) + warp; node < N_NODES;
         node += warpsPerGrid) {
        float acc[NCLS];
#pragma unroll
        for (int k = 0; k < NCLS; ++k) acc[k] = 0.0f;
        const float* hr = h + (size_t)node * DCAT;
#pragma unroll
        for (int j = 0; j < 4; ++j) {
            int cidx = j * 128 + lane * 4;
            float4 hv = *(const float4*)(hr + cidx);
            const float* w0 = &ws[(cidx + 0) * 17];
            const float* w1 = &ws[(cidx + 1) * 17];
            const float* w2 = &ws[(cidx + 2) * 17];
            const float* w3 = &ws[(cidx + 3) * 17];
#pragma unroll
            for (int k = 0; k < NCLS; ++k)
                acc[k] = fmaf(hv.x, w0[k], fmaf(hv.y, w1[k],
                         fmaf(hv.z, w2[k], fmaf(hv.w, w3[k], acc[k]))));
        }
#pragma unroll
        for (int off = 16; off > 0; off >>= 1) {
#pragma unroll
            for (int k = 0; k < NCLS; ++k)
                acc[k] += __shfl_xor_sync(0xffffffffu, acc[k], off);
        }
        if (lane == 0) {
            float* op = out + (size_t)node * NCLS;
#pragma unroll
            for (int k = 0; k < NCLS; ++k) op[k] = acc[k] + bs[k];
        }
    }
}

// ---------------------------------------------------------------------------
extern "C" void kernel_launch(void* const* d_in, const int* in_sizes, int n_in,
                              void* d_out, int out_size) {
    const float* x     = (const float*)d_in[0];
    const int*   ei    = (const int*)d_in[1];      // int32 (JAX x64 off)
    const float* W1    = (const float*)d_in[2];
    const float* b1    = (const float*)d_in[3];
    const float* W2    = (const float*)d_in[4];
    const float* b2    = (const float*)d_in[5];
    const float* W3    = (const float*)d_in[6];
    const float* b3    = (const float*)d_in[7];
    const float* W_lin = (const float*)d_in[8];
    const float* b_lin = (const float*)d_in[9];
    const float* bias[3] = {b1, b2, b3};

    float* labels = (float*)d_out;                      // [N, 16]
    float* h      = labels + (size_t)N_NODES * NCLS;    // [N, 512]

    const int TB = 256;
    k_init <<<(N_NODES * 32 + TB - 1) / TB, TB>>>(x, h);
    k_wconv<<<(3 * C * C + TB - 1) / TB, TB>>>(W1, W2, W3);
    k_deg  <<<(N_EDGES + TB - 1) / TB, TB>>>(ei);
    k_gemm_tc<<<(N_NODES + 127) / 128, 256>>>(h, 0);   // layer 1 GEMM
    k_scanA<<<NB, SB>>>();
    k_scanB<<<1, 128>>>();
    k_scanC<<<(N_NODES + TB - 1) / TB, TB>>>();
    k_fill <<<(N_EDGES + TB - 1) / TB, TB>>>(ei);

    k_aggr<<<(N_NODES * 64 + TB - 1) / TB, TB>>>(bias[0], h + 1 * C);
    for (int l = 1; l < 3; ++l) {
        k_gemm_tc<<<(N_NODES + 127) / 128, 256>>>(h + l * C, l);
        k_aggr<<<(N_NODES * 64 + TB - 1) / TB, TB>>>(bias[l], h + (l + 1) * C);
    }

    k_lin<<<2048, 256>>>(h, W_lin, b_lin, labels);
}

// round 8
// speedup vs baseline: 1.0109x; 1.0109x over previous
#include <cuda_runtime.h>
#include <cuda_bf16.h>

#define N_NODES 100000
#define N_EDGES 1600000
#define C       128
#define NCLS    16
#define DCAT    512   // 128 + 3*128
#define SB      1024
#define NB      ((N_NODES + SB - 1) / SB)   // 98 scan blocks

// ---- scratch (device globals: no allocation allowed) ----
__device__ float g_tmp[(size_t)N_NODES * C];   // x_prev @ W  (51.2 MB)
__device__ float g_dis[N_NODES];               // rsqrt(degree)
__device__ int   g_cnt[N_NODES];               // in-degree counts
__device__ int   g_rowstart[N_NODES + 1];      // CSR row offsets
__device__ int   g_cursor[N_NODES];            // fill cursors
__device__ int   g_bsum[NB];                   // scan block sums
__device__ int   g_boff[NB];                   // scan block offsets
__device__ int2  g_csr[N_EDGES];               // CSR: {src, dis[src] bits}
__device__ __nv_bfloat16 g_Wt_hi[3][C * C];    // W^T [n][k] hi, per layer
__device__ __nv_bfloat16 g_Wt_lo[3][C * C];    // W^T [n][k] lo, per layer

// ---------------------------------------------------------------------------
__global__ void k_init(const float* __restrict__ x, float* __restrict__ h) {
    int t = blockIdx.x * blockDim.x + threadIdx.x;
    if (t >= N_NODES * 32) return;
    int node = t >> 5;
    int lane = t & 31;
    float4 v = ((const float4*)(x + (size_t)node * C))[lane];
    ((float4*)(h + (size_t)node * DCAT))[lane] = v;
    if (lane == 0) g_cnt[node] = 0;
}

__global__ void k_wconv(const float* __restrict__ W0,
                        const float* __restrict__ W1,
                        const float* __restrict__ W2) {
    int idx = blockIdx.x * blockDim.x + threadIdx.x;
    if (idx >= 3 * C * C) return;
    int l = idx / (C * C);
    int r = idx - l * (C * C);
    const float* W = (l == 0) ? W0 : (l == 1) ? W1 : W2;
    int k = r >> 7;
    int n = r & 127;
    float v = W[r];
    __nv_bfloat16 hi = __float2bfloat16_rn(v);
    float lo = v - __bfloat162float(hi);
    g_Wt_hi[l][n * C + k] = hi;
    g_Wt_lo[l][n * C + k] = __float2bfloat16_rn(lo);
}

__global__ void k_deg(const int* __restrict__ ei) {
    int e = blockIdx.x * blockDim.x + threadIdx.x;
    if (e >= N_EDGES) return;
    atomicAdd(&g_cnt[ei[N_EDGES + e]], 1);
}

// ---------------------------------------------------------------------------
// Multi-block scan
// ---------------------------------------------------------------------------
__global__ void k_scanA() {
    int i = blockIdx.x * SB + threadIdx.x;
    int lane = threadIdx.x & 31, wid = threadIdx.x >> 5;
    int v = (i < N_NODES) ? g_cnt[i] : 0;
    int s = v;
#pragma unroll
    for (int o = 1; o < 32; o <<= 1) {
        int t = __shfl_up_sync(0xffffffffu, s, o);
        if (lane >= o) s += t;
    }
    __shared__ int wsum[32];
    if (lane == 31) wsum[wid] = s;
    __syncthreads();
    if (wid == 0) {
        int t = wsum[lane];
#pragma unroll
        for (int o = 1; o < 32; o <<= 1) {
            int u = __shfl_up_sync(0xffffffffu, t, o);
            if (lane >= o) t += u;
        }
        wsum[lane] = t;
    }
    __syncthreads();
    int incl = s + (wid > 0 ? wsum[wid - 1] : 0);
    if (i < N_NODES) g_rowstart[i] = incl - v;
    if (threadIdx.x == SB - 1) g_bsum[blockIdx.x] = incl;
}

__global__ void k_scanB() {
    int tid = threadIdx.x;
    int lane = tid & 31, wid = tid >> 5;
    int v = (tid < NB) ? g_bsum[tid] : 0;
    int s = v;
#pragma unroll
    for (int o = 1; o < 32; o <<= 1) {
        int t = __shfl_up_sync(0xffffffffu, s, o);
        if (lane >= o) s += t;
    }
    __shared__ int wsum[4];
    if (lane == 31) wsum[wid] = s;
    __syncthreads();
    int woff = 0;
    for (int w = 0; w < wid; ++w) woff += wsum[w];
    int incl = s + woff;
    if (tid < NB) g_boff[tid] = incl - v;
    if (tid == NB - 1) g_rowstart[N_NODES] = incl;
}

__global__ void k_scanC() {
    int i = blockIdx.x * blockDim.x + threadIdx.x;
    if (i >= N_NODES) return;
    int e = g_rowstart[i] + g_boff[i >> 10];
    g_rowstart[i] = e;
    g_cursor[i]   = e;
    g_dis[i]      = rsqrtf((float)(g_cnt[i] + 1));
}

__global__ void k_fill(const int* __restrict__ ei) {
    int e = blockIdx.x * blockDim.x + threadIdx.x;
    if (e >= N_EDGES) return;
    int s = ei[e];
    int d = ei[N_EDGES + e];
    int pos = atomicAdd(&g_cursor[d], 1);
    g_csr[pos] = make_int2(s, __float_as_int(g_dis[s]));
}

// ---------------------------------------------------------------------------
// GEMM v2: B resident in smem for whole kernel; A double-buffered;
// ONE __syncthreads per k-chunk; LDG of next chunk issued before MMAs.
// acc = hi@Whi + lo@Whi + hi@Wlo  (fp32 accumulate)
// ---------------------------------------------------------------------------
#define APAD  40
#define BPAD  136
struct GemmSmem {
    __nv_bfloat16 bh[128][BPAD];      // full-K B hi  [col][k]
    __nv_bfloat16 bl[128][BPAD];      // full-K B lo
    __nv_bfloat16 ah[2][128][APAD];   // A hi, double-buffered 32-k chunks
    __nv_bfloat16 al[2][128][APAD];
};
#define GEMM_SMEM_BYTES ((int)sizeof(GemmSmem))

__device__ __forceinline__ void mma_bf16(float c[4], const unsigned a[4],
                                         const unsigned b[2]) {
    asm volatile(
        "mma.sync.aligned.m16n8k16.row.col.f32.bf16.bf16.f32 "
        "{%0,%1,%2,%3}, {%4,%5,%6,%7}, {%8,%9}, {%0,%1,%2,%3};\n"
        : "+f"(c[0]), "+f"(c[1]), "+f"(c[2]), "+f"(c[3])
        : "r"(a[0]), "r"(a[1]), "r"(a[2]), "r"(a[3]), "r"(b[0]), "r"(b[1]));
}

__device__ __forceinline__ void cvt_split(const float av[16], unsigned ah[8],
                                          unsigned al[8]) {
#pragma unroll
    for (int j = 0; j < 8; ++j) {
        float v0 = av[2 * j], v1 = av[2 * j + 1];
        __nv_bfloat16 h0 = __float2bfloat16_rn(v0);
        __nv_bfloat16 h1 = __float2bfloat16_rn(v1);
        float l0 = v0 - __bfloat162float(h0);
        float l1 = v1 - __bfloat162float(h1);
        __nv_bfloat162 hp = __halves2bfloat162(h0, h1);
        __nv_bfloat162 lp = __halves2bfloat162(__float2bfloat16_rn(l0),
                                               __float2bfloat16_rn(l1));
        ah[j] = *(unsigned*)&hp;
        al[j] = *(unsigned*)&lp;
    }
}

__global__ void __launch_bounds__(256, 2)
k_gemm_tc(const float* __restrict__ in, int layer) {
    extern __shared__ char smem_raw[];
    GemmSmem& sm = *(GemmSmem*)smem_raw;

    const __nv_bfloat16* Whi = g_Wt_hi[layer];
    const __nv_bfloat16* Wlo = g_Wt_lo[layer];

    int tid  = threadIdx.x;
    int lane = tid & 31;
    int wid  = tid >> 5;
    int wm   = wid & 1;
    int wn   = wid >> 1;
    int row0 = blockIdx.x * 128;

    // A staging indices: thread -> (row, 16-k half of 32-chunk)
    int arow = tid >> 1;
    int akb  = (tid & 1) * 16;
    int grow = row0 + arow;
    if (grow >= N_NODES) grow = N_NODES - 1;
    const float* aptr = in + (size_t)grow * DCAT;

    // ---- load full B into smem (once) ----
    {
        int brow = tid >> 1;               // output col 0..127
        int bhalf = (tid & 1) * 64;        // k half
#pragma unroll
        for (int j = 0; j < 8; ++j) {
            *(uint4*)&sm.bh[brow][bhalf + j * 8] =
                *(const uint4*)&Whi[brow * C + bhalf + j * 8];
            *(uint4*)&sm.bl[brow][bhalf + j * 8] =
                *(const uint4*)&Wlo[brow * C + bhalf + j * 8];
        }
    }

    // ---- prologue: load + convert + stage chunk 0 ----
    float av[16];
#pragma unroll
    for (int j = 0; j < 4; ++j)
        *(float4*)&av[j * 4] = *(const float4*)(aptr + akb + j * 4);
    {
        unsigned ah[8], al[8];
        cvt_split(av, ah, al);
        *(uint4*)&sm.ah[0][arow][akb]     = make_uint4(ah[0], ah[1], ah[2], ah[3]);
        *(uint4*)&sm.ah[0][arow][akb + 8] = make_uint4(ah[4], ah[5], ah[6], ah[7]);
        *(uint4*)&sm.al[0][arow][akb]     = make_uint4(al[0], al[1], al[2], al[3]);
        *(uint4*)&sm.al[0][arow][akb + 8] = make_uint4(al[4], al[5], al[6], al[7]);
    }
    __syncthreads();

    float acc[4][4][4];
#pragma unroll
    for (int i = 0; i < 4; ++i)
#pragma unroll
        for (int j = 0; j < 4; ++j)
#pragma unroll
            for (int q = 0; q < 4; ++q) acc[i][j][q] = 0.0f;

#pragma unroll
    for (int c = 0; c < 4; ++c) {
        int p = c & 1;
        // issue gmem loads for next chunk BEFORE the MMAs
        if (c < 3) {
            int k0n = (c + 1) * 32;
#pragma unroll
            for (int j = 0; j < 4; ++j)
                *(float4*)&av[j * 4] = *(const float4*)(aptr + k0n + akb + j * 4);
        }

        // ---- MMAs on chunk c (stage p) ----
#pragma unroll
        for (int ks = 0; ks < 2; ++ks) {
            int kb  = ks * 16 + (lane & 3) * 2;          // A local k
            int kgb = c * 32 + kb;                        // B global k
            unsigned bh[4][2], bl[4][2];
#pragma unroll
            for (int ni = 0; ni < 4; ++ni) {
                int col = wn * 32 + ni * 8 + (lane >> 2);
                bh[ni][0] = *(unsigned*)&sm.bh[col][kgb];
                bh[ni][1] = *(unsigned*)&sm.bh[col][kgb + 8];
                bl[ni][0] = *(unsigned*)&sm.bl[col][kgb];
                bl[ni][1] = *(unsigned*)&sm.bl[col][kgb + 8];
            }
#pragma unroll
            for (int mi = 0; mi < 4; ++mi) {
                int r = wm * 64 + mi * 16 + (lane >> 2);
                unsigned AH[4], AL[4];
                AH[0] = *(unsigned*)&sm.ah[p][r][kb];
                AH[1] = *(unsigned*)&sm.ah[p][r + 8][kb];
                AH[2] = *(unsigned*)&sm.ah[p][r][kb + 8];
                AH[3] = *(unsigned*)&sm.ah[p][r + 8][kb + 8];
                AL[0] = *(unsigned*)&sm.al[p][r][kb];
                AL[1] = *(unsigned*)&sm.al[p][r + 8][kb];
                AL[2] = *(unsigned*)&sm.al[p][r][kb + 8];
                AL[3] = *(unsigned*)&sm.al[p][r + 8][kb + 8];
#pragma unroll
                for (int ni = 0; ni < 4; ++ni) {
                    mma_bf16(acc[mi][ni], AH, bh[ni]);
                    mma_bf16(acc[mi][ni], AL, bh[ni]);
                    mma_bf16(acc[mi][ni], AH, bl[ni]);
                }
            }
        }

        // ---- convert + stage chunk c+1 into other buffer ----
        if (c < 3) {
            unsigned ah[8], al[8];
            cvt_split(av, ah, al);
            int q = 1 - p;
            *(uint4*)&sm.ah[q][arow][akb]     = make_uint4(ah[0], ah[1], ah[2], ah[3]);
            *(uint4*)&sm.ah[q][arow][akb + 8] = make_uint4(ah[4], ah[5], ah[6], ah[7]);
            *(uint4*)&sm.al[q][arow][akb]     = make_uint4(al[0], al[1], al[2], al[3]);
            *(uint4*)&sm.al[q][arow][akb + 8] = make_uint4(al[4], al[5], al[6], al[7]);
            __syncthreads();
        }
    }

    // ---- store ----
#pragma unroll
    for (int mi = 0; mi < 4; ++mi) {
        int r = row0 + wm * 64 + mi * 16 + (lane >> 2);
#pragma unroll
        for (int ni = 0; ni < 4; ++ni) {
            int col = wn * 32 + ni * 8 + (lane & 3) * 2;
            if (r < N_NODES) {
                *(float2*)(g_tmp + (size_t)r * C + col) =
                    make_float2(acc[mi][ni][0], acc[mi][ni][1]);
            }
            if (r + 8 < N_NODES) {
                *(float2*)(g_tmp + (size_t)(r + 8) * C + col) =
                    make_float2(acc[mi][ni][2], acc[mi][ni][3]);
            }
        }
    }
}

// ---------------------------------------------------------------------------
// Aggregation: ONE warp per node (float4/lane), 4-edge explicit batching.
// ---------------------------------------------------------------------------
__global__ void k_aggr(const float* __restrict__ b, float* __restrict__ out) {
    int warp = (blockIdx.x * blockDim.x + threadIdx.x) >> 5;
    int lane = threadIdx.x & 31;
    if (warp >= N_NODES) return;

    int rs = g_rowstart[warp];
    int re = g_rowstart[warp + 1];
    float4 acc = make_float4(0.f, 0.f, 0.f, 0.f);

    int e = rs;
    for (; e + 4 <= re; e += 4) {
        int2 p0 = g_csr[e + 0];
        int2 p1 = g_csr[e + 1];
        int2 p2 = g_csr[e + 2];
        int2 p3 = g_csr[e + 3];
        float4 v0 = ((const float4*)(g_tmp + (size_t)p0.x * C))[lane];
        float4 v1 = ((const float4*)(g_tmp + (size_t)p1.x * C))[lane];
        float4 v2 = ((const float4*)(g_tmp + (size_t)p2.x * C))[lane];
        float4 v3 = ((const float4*)(g_tmp + (size_t)p3.x * C))[lane];
        float w0 = __int_as_float(p0.y), w1 = __int_as_float(p1.y);
        float w2 = __int_as_float(p2.y), w3 = __int_as_float(p3.y);
        acc.x = fmaf(v0.x, w0, fmaf(v1.x, w1, fmaf(v2.x, w2, fmaf(v3.x, w3, acc.x))));
        acc.y = fmaf(v0.y, w0, fmaf(v1.y, w1, fmaf(v2.y, w2, fmaf(v3.y, w3, acc.y))));
        acc.z = fmaf(v0.z, w0, fmaf(v1.z, w1, fmaf(v2.z, w2, fmaf(v3.z, w3, acc.z))));
        acc.w = fmaf(v0.w, w0, fmaf(v1.w, w1, fmaf(v2.w, w2, fmaf(v3.w, w3, acc.w))));
    }
    for (; e < re; ++e) {
        int2 p = g_csr[e];
        float w = __int_as_float(p.y);
        float4 v = ((const float4*)(g_tmp + (size_t)p.x * C))[lane];
        acc.x = fmaf(v.x, w, acc.x);
        acc.y = fmaf(v.y, w, acc.y);
        acc.z = fmaf(v.z, w, acc.z);
        acc.w = fmaf(v.w, w, acc.w);
    }

    float di = g_dis[warp];
    float d2 = di * di;
    float4 sv = ((const float4*)(g_tmp + (size_t)warp * C))[lane];
    float4 bb = ((const float4*)b)[lane];
    float4 o;
    o.x = fmaf(acc.x, di, fmaf(sv.x, d2, bb.x));
    o.y = fmaf(acc.y, di, fmaf(sv.y, d2, bb.y));
    o.z = fmaf(acc.z, di, fmaf(sv.z, d2, bb.z));
    o.w = fmaf(acc.w, di, fmaf(sv.w, d2, bb.w));
    ((float4*)(out + (size_t)warp * DCAT))[lane] = o;
}

// ---------------------------------------------------------------------------
// Final linear: labels[N,16] = h[N,512] @ W_lin[512,16] + b_lin
// ---------------------------------------------------------------------------
__global__ void k_lin(const float* __restrict__ h, const float* __restrict__ Wl,
                      const float* __restrict__ bl, float* __restrict__ out) {
    __shared__ float ws[DCAT * 17];
    __shared__ float bs[NCLS];
    for (int idx = threadIdx.x; idx < DCAT * NCLS; idx += blockDim.x) {
        int c = idx >> 4;
        int k = idx & 15;
        ws[c * 17 + k] = Wl[idx];
    }
    if (threadIdx.x < NCLS) bs[threadIdx.x] = bl[threadIdx.x];
    __syncthreads();

    int warp = threadIdx.x >> 5;
    int lane = threadIdx.x & 31;
    int warpsPerGrid = (blockDim.x >> 5) * gridDim.x;
    for (int node = blockIdx.x * (blockDim.x >> 5) + warp; node < N_NODES;
         node += warpsPerGrid) {
        float acc[NCLS];
#pragma unroll
        for (int k = 0; k < NCLS; ++k) acc[k] = 0.0f;
        const float* hr = h + (size_t)node * DCAT;
#pragma unroll
        for (int j = 0; j < 4; ++j) {
            int cidx = j * 128 + lane * 4;
            float4 hv = *(const float4*)(hr + cidx);
            const float* w0 = &ws[(cidx + 0) * 17];
            const float* w1 = &ws[(cidx + 1) * 17];
            const float* w2 = &ws[(cidx + 2) * 17];
            const float* w3 = &ws[(cidx + 3) * 17];
#pragma unroll
            for (int k = 0; k < NCLS; ++k)
                acc[k] = fmaf(hv.x, w0[k], fmaf(hv.y, w1[k],
                         fmaf(hv.z, w2[k], fmaf(hv.w, w3[k], acc[k]))));
        }
#pragma unroll
        for (int off = 16; off > 0; off >>= 1) {
#pragma unroll
            for (int k = 0; k < NCLS; ++k)
                acc[k] += __shfl_xor_sync(0xffffffffu, acc[k], off);
        }
        if (lane == 0) {
            float* op = out + (size_t)node * NCLS;
#pragma unroll
            for (int k = 0; k < NCLS; ++k) op[k] = acc[k] + bs[k];
        }
    }
}

// ---------------------------------------------------------------------------
extern "C" void kernel_launch(void* const* d_in, const int* in_sizes, int n_in,
                              void* d_out, int out_size) {
    const float* x     = (const float*)d_in[0];
    const int*   ei    = (const int*)d_in[1];      // int32 (JAX x64 off)
    const float* W1    = (const float*)d_in[2];
    const float* b1    = (const float*)d_in[3];
    const float* W2    = (const float*)d_in[4];
    const float* b2    = (const float*)d_in[5];
    const float* W3    = (const float*)d_in[6];
    const float* b3    = (const float*)d_in[7];
    const float* W_lin = (const float*)d_in[8];
    const float* b_lin = (const float*)d_in[9];
    const float* bias[3] = {b1, b2, b3};

    float* labels = (float*)d_out;                      // [N, 16]
    float* h      = labels + (size_t)N_NODES * NCLS;    // [N, 512]

    static int smem_set = 0;
    if (!smem_set) {
        cudaFuncSetAttribute(k_gemm_tc,
                             cudaFuncAttributeMaxDynamicSharedMemorySize,
                             GEMM_SMEM_BYTES);
        smem_set = 1;
    }

    const int TB = 256;
    k_init <<<(N_NODES * 32 + TB - 1) / TB, TB>>>(x, h);
    k_wconv<<<(3 * C * C + TB - 1) / TB, TB>>>(W1, W2, W3);
    k_deg  <<<(N_EDGES + TB - 1) / TB, TB>>>(ei);
    k_gemm_tc<<<(N_NODES + 127) / 128, 256, GEMM_SMEM_BYTES>>>(h, 0);
    k_scanA<<<NB, SB>>>();
    k_scanB<<<1, 128>>>();
    k_scanC<<<(N_NODES + TB - 1) / TB, TB>>>();
    k_fill <<<(N_EDGES + TB - 1) / TB, TB>>>(ei);

    k_aggr<<<(N_NODES * 32 + TB - 1) / TB, TB>>>(bias[0], h + 1 * C);
    for (int l = 1; l < 3; ++l) {
        k_gemm_tc<<<(N_NODES + 127) / 128, 256, GEMM_SMEM_BYTES>>>(h + l * C, l);
        k_aggr<<<(N_NODES * 32 + TB - 1) / TB, TB>>>(bias[l], h + (l + 1) * C);
    }

    k_lin<<<2048, 256>>>(h, W_lin, b_lin, labels);
}

// round 10
// speedup vs baseline: 1.1016x; 1.0897x over previous
#include <cuda_runtime.h>
#include <cuda_bf16.h>
#include <cuda_fp16.h>

#define N_NODES 100000
#define N_EDGES 1600000
#define C       128
#define NCLS    16
#define DCAT    512   // 128 + 3*128
#define SB      1024
#define NB      ((N_NODES + SB - 1) / SB)   // 98 scan blocks

// ---- scratch (device globals: no allocation allowed) ----
__device__ float  g_tmp[(size_t)N_NODES * C];    // x_prev @ W  fp32 (51.2 MB)
__device__ __half g_tmp16[(size_t)N_NODES * C];  // same, fp16 (25.6 MB)
__device__ float  g_dis[N_NODES];                // rsqrt(degree)
__device__ int    g_cnt[N_NODES];                // in-degree counts
__device__ int    g_rowstart[N_NODES + 1];       // CSR row offsets
__device__ int    g_cursor[N_NODES];             // fill cursors
__device__ int    g_bsum[NB];                    // scan block sums
__device__ int    g_boff[NB];                    // scan block offsets
__device__ int2   g_csr[N_EDGES];                // CSR: {src, dis[src] bits}
__device__ __nv_bfloat16 g_Wt_hi[3][C * C];      // W^T [n][k] hi, per layer
__device__ __nv_bfloat16 g_Wt_lo[3][C * C];      // W^T [n][k] lo, per layer

// ---------------------------------------------------------------------------
__global__ void k_init(const float* __restrict__ x, float* __restrict__ h) {
    int t = blockIdx.x * blockDim.x + threadIdx.x;
    if (t >= N_NODES * 32) return;
    int node = t >> 5;
    int lane = t & 31;
    float4 v = ((const float4*)(x + (size_t)node * C))[lane];
    ((float4*)(h + (size_t)node * DCAT))[lane] = v;
    if (lane == 0) g_cnt[node] = 0;
}

__global__ void k_wconv(const float* __restrict__ W0,
                        const float* __restrict__ W1,
                        const float* __restrict__ W2) {
    int idx = blockIdx.x * blockDim.x + threadIdx.x;
    if (idx >= 3 * C * C) return;
    int l = idx / (C * C);
    int r = idx - l * (C * C);
    const float* W = (l == 0) ? W0 : (l == 1) ? W1 : W2;
    int k = r >> 7;
    int n = r & 127;
    float v = W[r];
    __nv_bfloat16 hi = __float2bfloat16_rn(v);
    float lo = v - __bfloat162float(hi);
    g_Wt_hi[l][n * C + k] = hi;
    g_Wt_lo[l][n * C + k] = __float2bfloat16_rn(lo);
}

__global__ void k_deg(const int* __restrict__ ei) {
    int e = blockIdx.x * blockDim.x + threadIdx.x;
    if (e >= N_EDGES) return;
    atomicAdd(&g_cnt[ei[N_EDGES + e]], 1);
}

// ---------------------------------------------------------------------------
// Multi-block scan
// ---------------------------------------------------------------------------
__global__ void k_scanA() {
    int i = blockIdx.x * SB + threadIdx.x;
    int lane = threadIdx.x & 31, wid = threadIdx.x >> 5;
    int v = (i < N_NODES) ? g_cnt[i] : 0;
    int s = v;
#pragma unroll
    for (int o = 1; o < 32; o <<= 1) {
        int t = __shfl_up_sync(0xffffffffu, s, o);
        if (lane >= o) s += t;
    }
    __shared__ int wsum[32];
    if (lane == 31) wsum[wid] = s;
    __syncthreads();
    if (wid == 0) {
        int t = wsum[lane];
#pragma unroll
        for (int o = 1; o < 32; o <<= 1) {
            int u = __shfl_up_sync(0xffffffffu, t, o);
            if (lane >= o) t += u;
        }
        wsum[lane] = t;
    }
    __syncthreads();
    int incl = s + (wid > 0 ? wsum[wid - 1] : 0);
    if (i < N_NODES) g_rowstart[i] = incl - v;
    if (threadIdx.x == SB - 1) g_bsum[blockIdx.x] = incl;
}

__global__ void k_scanB() {
    int tid = threadIdx.x;
    int lane = tid & 31, wid = tid >> 5;
    int v = (tid < NB) ? g_bsum[tid] : 0;
    int s = v;
#pragma unroll
    for (int o = 1; o < 32; o <<= 1) {
        int t = __shfl_up_sync(0xffffffffu, s, o);
        if (lane >= o) s += t;
    }
    __shared__ int wsum[4];
    if (lane == 31) wsum[wid] = s;
    __syncthreads();
    int woff = 0;
    for (int w = 0; w < wid; ++w) woff += wsum[w];
    int incl = s + woff;
    if (tid < NB) g_boff[tid] = incl - v;
    if (tid == NB - 1) g_rowstart[N_NODES] = incl;
}

__global__ void k_scanC() {
    int i = blockIdx.x * blockDim.x + threadIdx.x;
    if (i >= N_NODES) return;
    int e = g_rowstart[i] + g_boff[i >> 10];
    g_rowstart[i] = e;
    g_cursor[i]   = e;
    g_dis[i]      = rsqrtf((float)(g_cnt[i] + 1));
}

__global__ void k_fill(const int* __restrict__ ei) {
    int e = blockIdx.x * blockDim.x + threadIdx.x;
    if (e >= N_EDGES) return;
    int s = ei[e];
    int d = ei[N_EDGES + e];
    int pos = atomicAdd(&g_cursor[d], 1);
    g_csr[pos] = make_int2(s, __float_as_int(g_dis[s]));
}

// ---------------------------------------------------------------------------
// GEMM (round-6 version + fp16 mirror store in epilogue)
// acc = hi@Whi + lo@Whi + hi@Wlo  (fp32 accumulate)
// ---------------------------------------------------------------------------
#define APAD 40
__device__ __forceinline__ void mma_bf16(float c[4], const unsigned a[4],
                                         const unsigned b[2]) {
    asm volatile(
        "mma.sync.aligned.m16n8k16.row.col.f32.bf16.bf16.f32 "
        "{%0,%1,%2,%3}, {%4,%5,%6,%7}, {%8,%9}, {%0,%1,%2,%3};\n"
        : "+f"(c[0]), "+f"(c[1]), "+f"(c[2]), "+f"(c[3])
        : "r"(a[0]), "r"(a[1]), "r"(a[2]), "r"(a[3]), "r"(b[0]), "r"(b[1]));
}

__global__ void __launch_bounds__(256)
k_gemm_tc(const float* __restrict__ in, int layer) {
    __shared__ __nv_bfloat16 a_hi[128][APAD];
    __shared__ __nv_bfloat16 a_lo[128][APAD];
    __shared__ __nv_bfloat16 b_hi[128][APAD];
    __shared__ __nv_bfloat16 b_lo[128][APAD];

    const __nv_bfloat16* Whi = g_Wt_hi[layer];
    const __nv_bfloat16* Wlo = g_Wt_lo[layer];

    int tid  = threadIdx.x;
    int lane = tid & 31;
    int wid  = tid >> 5;
    int wm   = wid & 1;
    int wn   = wid >> 1;
    int row0 = blockIdx.x * 128;

    int arow = tid >> 1;
    int akb  = (tid & 1) * 16;
    int grow = row0 + arow;
    if (grow >= N_NODES) grow = N_NODES - 1;
    const float* aptr = in + (size_t)grow * DCAT;

    int bcol = tid >> 1;
    int bkb  = (tid & 1) * 16;

    float acc[4][4][4];
#pragma unroll
    for (int i = 0; i < 4; ++i)
#pragma unroll
        for (int j = 0; j < 4; ++j)
#pragma unroll
            for (int q = 0; q < 4; ++q) acc[i][j][q] = 0.0f;

    for (int k0 = 0; k0 < C; k0 += 32) {
        float av[16];
#pragma unroll
        for (int j = 0; j < 4; ++j) {
            float4 v = *(const float4*)(aptr + k0 + akb + j * 4);
            av[j * 4 + 0] = v.x; av[j * 4 + 1] = v.y;
            av[j * 4 + 2] = v.z; av[j * 4 + 3] = v.w;
        }
        uint4 wv_hi0 = *(const uint4*)(&Whi[bcol * C + k0 + bkb]);
        uint4 wv_hi1 = *(const uint4*)(&Whi[bcol * C + k0 + bkb + 8]);
        uint4 wv_lo0 = *(const uint4*)(&Wlo[bcol * C + k0 + bkb]);
        uint4 wv_lo1 = *(const uint4*)(&Wlo[bcol * C + k0 + bkb + 8]);

        unsigned ah[8], al[8];
#pragma unroll
        for (int j = 0; j < 8; ++j) {
            float v0 = av[2 * j], v1 = av[2 * j + 1];
            __nv_bfloat16 h0 = __float2bfloat16_rn(v0);
            __nv_bfloat16 h1 = __float2bfloat16_rn(v1);
            float l0 = v0 - __bfloat162float(h0);
            float l1 = v1 - __bfloat162float(h1);
            __nv_bfloat162 hp = __halves2bfloat162(h0, h1);
            __nv_bfloat162 lp = __halves2bfloat162(__float2bfloat16_rn(l0),
                                                   __float2bfloat16_rn(l1));
            ah[j] = *(unsigned*)&hp;
            al[j] = *(unsigned*)&lp;
        }

        __syncthreads();
        *(uint4*)&a_hi[arow][akb]     = make_uint4(ah[0], ah[1], ah[2], ah[3]);
        *(uint4*)&a_hi[arow][akb + 8] = make_uint4(ah[4], ah[5], ah[6], ah[7]);
        *(uint4*)&a_lo[arow][akb]     = make_uint4(al[0], al[1], al[2], al[3]);
        *(uint4*)&a_lo[arow][akb + 8] = make_uint4(al[4], al[5], al[6], al[7]);
        *(uint4*)&b_hi[bcol][bkb]     = wv_hi0;
        *(uint4*)&b_hi[bcol][bkb + 8] = wv_hi1;
        *(uint4*)&b_lo[bcol][bkb]     = wv_lo0;
        *(uint4*)&b_lo[bcol][bkb + 8] = wv_lo1;
        __syncthreads();

#pragma unroll
        for (int ks = 0; ks < 2; ++ks) {
            int kb = ks * 16 + (lane & 3) * 2;
            unsigned bh[4][2], bl[4][2];
#pragma unroll
            for (int ni = 0; ni < 4; ++ni) {
                int col = wn * 32 + ni * 8 + (lane >> 2);
                bh[ni][0] = *(unsigned*)&b_hi[col][kb];
                bh[ni][1] = *(unsigned*)&b_hi[col][kb + 8];
                bl[ni][0] = *(unsigned*)&b_lo[col][kb];
                bl[ni][1] = *(unsigned*)&b_lo[col][kb + 8];
            }
#pragma unroll
            for (int mi = 0; mi < 4; ++mi) {
                int r = wm * 64 + mi * 16 + (lane >> 2);
                unsigned AH[4], AL[4];
                AH[0] = *(unsigned*)&a_hi[r][kb];
                AH[1] = *(unsigned*)&a_hi[r + 8][kb];
                AH[2] = *(unsigned*)&a_hi[r][kb + 8];
                AH[3] = *(unsigned*)&a_hi[r + 8][kb + 8];
                AL[0] = *(unsigned*)&a_lo[r][kb];
                AL[1] = *(unsigned*)&a_lo[r + 8][kb];
                AL[2] = *(unsigned*)&a_lo[r][kb + 8];
                AL[3] = *(unsigned*)&a_lo[r + 8][kb + 8];
#pragma unroll
                for (int ni = 0; ni < 4; ++ni) {
                    mma_bf16(acc[mi][ni], AH, bh[ni]);
                    mma_bf16(acc[mi][ni], AL, bh[ni]);
                    mma_bf16(acc[mi][ni], AH, bl[ni]);
                }
            }
        }
    }

#pragma unroll
    for (int mi = 0; mi < 4; ++mi) {
        int r = row0 + wm * 64 + mi * 16 + (lane >> 2);
#pragma unroll
        for (int ni = 0; ni < 4; ++ni) {
            int col = wn * 32 + ni * 8 + (lane & 3) * 2;
            if (r < N_NODES) {
                *(float2*)(g_tmp + (size_t)r * C + col) =
                    make_float2(acc[mi][ni][0], acc[mi][ni][1]);
                *(__half2*)(g_tmp16 + (size_t)r * C + col) =
                    __floats2half2_rn(acc[mi][ni][0], acc[mi][ni][1]);
            }
            if (r + 8 < N_NODES) {
                *(float2*)(g_tmp + (size_t)(r + 8) * C + col) =
                    make_float2(acc[mi][ni][2], acc[mi][ni][3]);
                *(__half2*)(g_tmp16 + (size_t)(r + 8) * C + col) =
                    __floats2half2_rn(acc[mi][ni][2], acc[mi][ni][3]);
            }
        }
    }
}

// ---------------------------------------------------------------------------
// Aggregation: one warp per node; fp16 gather (halves L2 sector traffic),
// fp32 accumulate; self-loop term read fp32-exact.
// ---------------------------------------------------------------------------
__global__ void k_aggr(const float* __restrict__ b, float* __restrict__ out) {
    int warp = (blockIdx.x * blockDim.x + threadIdx.x) >> 5;
    int lane = threadIdx.x & 31;
    if (warp >= N_NODES) return;

    int rs = g_rowstart[warp];
    int re = g_rowstart[warp + 1];
    int off = lane * 4;
    float4 acc = make_float4(0.f, 0.f, 0.f, 0.f);

#pragma unroll 4
    for (int e = rs; e < re; ++e) {
        int2  p = g_csr[e];
        float w = __int_as_float(p.y);
        uint2 u = *(const uint2*)(g_tmp16 + (size_t)p.x * C + off);  // 4 halves
        float2 v01 = __half22float2(*(__half2*)&u.x);
        float2 v23 = __half22float2(*(__half2*)&u.y);
        acc.x = fmaf(v01.x, w, acc.x);
        acc.y = fmaf(v01.y, w, acc.y);
        acc.z = fmaf(v23.x, w, acc.z);
        acc.w = fmaf(v23.y, w, acc.w);
    }

    float di = g_dis[warp];
    float d2 = di * di;
    float4 sv = ((const float4*)(g_tmp + (size_t)warp * C))[lane];  // fp32 exact
    float4 bb = ((const float4*)b)[lane];
    float4 o;
    o.x = fmaf(acc.x, di, fmaf(sv.x, d2, bb.x));
    o.y = fmaf(acc.y, di, fmaf(sv.y, d2, bb.y));
    o.z = fmaf(acc.z, di, fmaf(sv.z, d2, bb.z));
    o.w = fmaf(acc.w, di, fmaf(sv.w, d2, bb.w));
    ((float4*)(out + (size_t)warp * DCAT))[lane] = o;
}

// ---------------------------------------------------------------------------
// Final linear: labels[N,16] = h[N,512] @ W_lin[512,16] + b_lin
// ---------------------------------------------------------------------------
__global__ void k_lin(const float* __restrict__ h, const float* __restrict__ Wl,
                      const float* __restrict__ bl, float* __restrict__ out) {
    __shared__ float ws[DCAT * 17];
    __shared__ float bs[NCLS];
    for (int idx = threadIdx.x; idx < DCAT * NCLS; idx += blockDim.x) {
        int c = idx >> 4;
        int k = idx & 15;
        ws[c * 17 + k] = Wl[idx];
    }
    if (threadIdx.x < NCLS) bs[threadIdx.x] = bl[threadIdx.x];
    __syncthreads();

    int warp = threadIdx.x >> 5;
    int lane = threadIdx.x & 31;
    int warpsPerGrid = (blockDim.x >> 5) * gridDim.x;
    for (int node = blockIdx.x * (blockDim.x >> 5) + warp; node < N_NODES;
         node += warpsPerGrid) {
        float acc[NCLS];
#pragma unroll
        for (int k = 0; k < NCLS; ++k) acc[k] = 0.0f;
        const float* hr = h + (size_t)node * DCAT;
#pragma unroll
        for (int j = 0; j < 4; ++j) {
            int cidx = j * 128 + lane * 4;
            float4 hv = *(const float4*)(hr + cidx);
            const float* w0 = &ws[(cidx + 0) * 17];
            const float* w1 = &ws[(cidx + 1) * 17];
            const float* w2 = &ws[(cidx + 2) * 17];
            const float* w3 = &ws[(cidx + 3) * 17];
#pragma unroll
            for (int k = 0; k < NCLS; ++k)
                acc[k] = fmaf(hv.x, w0[k], fmaf(hv.y, w1[k],
                         fmaf(hv.z, w2[k], fmaf(hv.w, w3[k], acc[k]))));
        }
#pragma unroll
        for (int off = 16; off > 0; off >>= 1) {
#pragma unroll
            for (int k = 0; k < NCLS; ++k)
                acc[k] += __shfl_xor_sync(0xffffffffu, acc[k], off);
        }
        if (lane == 0) {
            float* op = out + (size_t)node * NCLS;
#pragma unroll
            for (int k = 0; k < NCLS; ++k) op[k] = acc[k] + bs[k];
        }
    }
}

// ---------------------------------------------------------------------------
extern "C" void kernel_launch(void* const* d_in, const int* in_sizes, int n_in,
                              void* d_out, int out_size) {
    const float* x     = (const float*)d_in[0];
    const int*   ei    = (const int*)d_in[1];      // int32 (JAX x64 off)
    const float* W1    = (const float*)d_in[2];
    const float* b1    = (const float*)d_in[3];
    const float* W2    = (const float*)d_in[4];
    const float* b2    = (const float*)d_in[5];
    const float* W3    = (const float*)d_in[6];
    const float* b3    = (const float*)d_in[7];
    const float* W_lin = (const float*)d_in[8];
    const float* b_lin = (const float*)d_in[9];
    const float* bias[3] = {b1, b2, b3};

    float* labels = (float*)d_out;                      // [N, 16]
    float* h      = labels + (size_t)N_NODES * NCLS;    // [N, 512]

    const int TB = 256;
    k_init <<<(N_NODES * 32 + TB - 1) / TB, TB>>>(x, h);
    k_wconv<<<(3 * C * C + TB - 1) / TB, TB>>>(W1, W2, W3);
    k_deg  <<<(N_EDGES + TB - 1) / TB, TB>>>(ei);
    k_gemm_tc<<<(N_NODES + 127) / 128, 256>>>(h, 0);   // layer 1 GEMM
    k_scanA<<<NB, SB>>>();
    k_scanB<<<1, 128>>>();
    k_scanC<<<(N_NODES + TB - 1) / TB, TB>>>();
    k_fill <<<(N_EDGES + TB - 1) / TB, TB>>>(ei);

    k_aggr<<<(N_NODES * 32 + TB - 1) / TB, TB>>>(bias[0], h + 1 * C);
    for (int l = 1; l < 3; ++l) {
        k_gemm_tc<<<(N_NODES + 127) / 128, 256>>>(h + l * C, l);
        k_aggr<<<(N_NODES * 32 + TB - 1) / TB, TB>>>(bias[l], h + (l + 1) * C);
    }

    k_lin<<<2048, 256>>>(h, W_lin, b_lin, labels);
}